// round 9
// baseline (speedup 1.0000x reference)
#include <cuda_runtime.h>
#include <cuda_bf16.h>
#include <cstdint>

// Problem dims
constexpr int BS  = 32;
constexpr int SEQ = 2048;
constexpr int IN  = 512;
constexpr int H   = 256;
constexpr int M0  = BS * SEQ;          // 65536 rows
constexpr int XXSZ = BS * SEQ * 2 * H; // 33554432 floats (xx output)

constexpr int WFC_N = H * IN;          // 131072
constexpr int W2_N  = 2 * H * H;       // 131072

// ---------------- scratch (device globals; no allocation allowed) -----------
__device__ float g_H1[M0 * H];       // input projection  (64 MB)
__device__ float g_G0[M0 * H];       // layer-0 gates     (64 MB)
__device__ float g_Y0[2 * M0 * H];   // layer-0 outputs, ltr then rtl (128 MB)
__device__ float g_G1[2 * M0 * H];   // layer-1 gates     (128 MB)
__device__ float g_Wr[WFC_N + W2_N]; // tf32-prerounded weights (1 MB)

// ---------------- small helpers ---------------------------------------------
__device__ __forceinline__ uint32_t f2tf(float x) {
    uint32_t u;
    asm("cvt.rna.tf32.f32 %0, %1;" : "=r"(u) : "f"(x));
    return u;
}

__device__ __forceinline__ void cp16(float* s, const float* g) {
    uint32_t sa = (uint32_t)__cvta_generic_to_shared(s);
    asm volatile("cp.async.cg.shared.global [%0], [%1], 16;\n" :: "r"(sa), "l"(g));
}
__device__ __forceinline__ void cp_commit() {
    asm volatile("cp.async.commit_group;\n" ::: "memory");
}
__device__ __forceinline__ void cp_wait1() {
    asm volatile("cp.async.wait_group 1;\n" ::: "memory");
}
__device__ __forceinline__ void cp_wait0() {
    asm volatile("cp.async.wait_group 0;\n" ::: "memory");
}

__device__ __forceinline__ void mma_tf32(float c[4], const uint32_t a[4], const uint32_t b[2]) {
    asm volatile(
        "mma.sync.aligned.m16n8k8.row.col.f32.tf32.tf32.f32 "
        "{%0,%1,%2,%3}, {%4,%5,%6,%7}, {%8,%9}, {%0,%1,%2,%3};\n"
        : "+f"(c[0]), "+f"(c[1]), "+f"(c[2]), "+f"(c[3])
        : "r"(a[0]), "r"(a[1]), "r"(a[2]), "r"(a[3]), "r"(b[0]), "r"(b[1]));
}

// accurate-enough tanh pieces: ex2.approx + rcp.approx (rel err ~1e-6)
__device__ __forceinline__ float ex2f(float z) {
    float e; asm("ex2.approx.f32 %0, %1;" : "=f"(e) : "f"(z)); return e;
}
__device__ __forceinline__ float rcpf(float d) {
    float r; asm("rcp.approx.f32 %0, %1;" : "=f"(r) : "f"(d)); return r;
}

// ---------------- weight pre-round to tf32 (bitwise == cvt.rna per use) -----
__global__ void round_w_kernel(const float* __restrict__ Wfc,
                               const float* __restrict__ W2,
                               float* __restrict__ out) {
    int i = blockIdx.x * blockDim.x + threadIdx.x;
    if (i < WFC_N) {
        out[i] = __uint_as_float(f2tf(Wfc[i]));
    } else if (i < WFC_N + W2_N) {
        out[i] = __uint_as_float(f2tf(W2[i - WFC_N]));
    }
}

// ---------------- GEMM: C[M,256] = act(A[M,K] @ W[256,K]^T + bias) ----------
// tiles: 128x128x32, 256 threads = 8 warps laid out 4(m) x 2(n),
// warp tile 32x64. W is pre-rounded tf32 -> B frags need no cvt.
constexpr int TBM = 128, TBN = 128, TBK = 32, LDT = 36;
constexpr int GEMM_SMEM = 2 * 2 * TBM * LDT * (int)sizeof(float);  // 73728 B

template <int ACT>
__launch_bounds__(256, 2)
__global__ void gemm_kernel(const float* __restrict__ A, const float* __restrict__ W,
                            const float* __restrict__ bias, float* __restrict__ C,
                            int M, int K) {
    extern __shared__ float smem[];
    float* As = smem;                 // [2][128][36]
    float* Bs = smem + 2 * TBM * LDT; // [2][128][36]

    const int tid  = threadIdx.x;
    const int warp = tid >> 5, lane = tid & 31;
    const int wm = (warp >> 1) * 32;   // 4 distinct m-slabs (A redundancy 2x)
    const int wn = (warp & 1) * 64;    // 2 distinct n-slabs
    const int bm = blockIdx.x * TBM;
    const int bn = blockIdx.y * TBN;

    float acc[2][8][4];
#pragma unroll
    for (int i = 0; i < 2; i++)
#pragma unroll
        for (int j = 0; j < 8; j++)
#pragma unroll
            for (int k = 0; k < 4; k++) acc[i][j][k] = 0.f;

    auto load_tile = [&](int kt, int buf) {
        const float* Ag = A + bm * K + kt * TBK;
        const float* Wg = W + bn * K + kt * TBK;
        float* Asb = As + buf * TBM * LDT;
        float* Bsb = Bs + buf * TBM * LDT;
#pragma unroll
        for (int i = 0; i < 4; i++) {
            int idx = i * 256 + tid;
            int row = idx >> 3, c4 = (idx & 7) * 4;
            cp16(Asb + row * LDT + c4, Ag + row * K + c4);
            cp16(Bsb + row * LDT + c4, Wg + row * K + c4);
        }
    };

    const int KT = K / TBK;
    load_tile(0, 0);
    cp_commit();

    for (int kt = 0; kt < KT; kt++) {
        const int cur = kt & 1;
        if (kt + 1 < KT) {
            load_tile(kt + 1, cur ^ 1);
            cp_commit();
            cp_wait1();
        } else {
            cp_wait0();
        }
        __syncthreads();

        const float* __restrict__ Asb = As + cur * TBM * LDT;
        const float* __restrict__ Bsb = Bs + cur * TBM * LDT;
        const int r0 = wm + (lane >> 2);
        const int kc = lane & 3;
#pragma unroll
        for (int kk = 0; kk < 4; kk++) {
            uint32_t a[2][4], b[8][2];
#pragma unroll
            for (int mi = 0; mi < 2; mi++) {
                int r = r0 + mi * 16;
                a[mi][0] = f2tf(Asb[r * LDT + kk * 8 + kc]);
                a[mi][1] = f2tf(Asb[(r + 8) * LDT + kk * 8 + kc]);
                a[mi][2] = f2tf(Asb[r * LDT + kk * 8 + kc + 4]);
                a[mi][3] = f2tf(Asb[(r + 8) * LDT + kk * 8 + kc + 4]);
            }
#pragma unroll
            for (int ni = 0; ni < 8; ni++) {
                int n = wn + ni * 8 + (lane >> 2);
                // weights pre-rounded to tf32: raw bits are already canonical
                b[ni][0] = __float_as_uint(Bsb[n * LDT + kk * 8 + kc]);
                b[ni][1] = __float_as_uint(Bsb[n * LDT + kk * 8 + kc + 4]);
            }
#pragma unroll
            for (int mi = 0; mi < 2; mi++)
#pragma unroll
                for (int ni = 0; ni < 8; ni++) mma_tf32(acc[mi][ni], a[mi], b[ni]);
        }
        __syncthreads();
    }

    // epilogue: bias (+ sigmoid)
#pragma unroll
    for (int mi = 0; mi < 2; mi++) {
        int row = bm + wm + mi * 16 + (lane >> 2);
#pragma unroll
        for (int ni = 0; ni < 8; ni++) {
            int col = bn + wn + ni * 8 + (lane & 3) * 2;
            float b0 = bias[col], b1 = bias[col + 1];
            float v0 = acc[mi][ni][0] + b0;
            float v1 = acc[mi][ni][1] + b1;
            float v2 = acc[mi][ni][2] + b0;
            float v3 = acc[mi][ni][3] + b1;
            if (ACT) {
                v0 = 1.f / (1.f + __expf(-v0));
                v1 = 1.f / (1.f + __expf(-v1));
                v2 = 1.f / (1.f + __expf(-v2));
                v3 = 1.f / (1.f + __expf(-v3));
            }
            *(float2*)(C + row * 256 + col)       = make_float2(v0, v1);
            *(float2*)(C + (row + 8) * 256 + col) = make_float2(v2, v3);
        }
    }
}

// ---------------- bidirectional scan, one direction per thread --------------
// 16384 independent chains (8192 (b,f) pairs x 2 directions). blockIdx.y picks
// the direction so each thread owns ONE clean serial chain:
//   fma -> mul -> ex2 -> add -> rcp -> fma  (~48 cyc/step)
// 16-deep register prefetch covers DRAM latency; final block peeled.
constexpr int PF = 16;
constexpr float C2LOG2E = 2.8853900817779268f;  // 2*log2(e)

__launch_bounds__(64, 16)
__global__ void scan_dir_kernel(
    const float* __restrict__ Xl, const float* __restrict__ Gl, float* __restrict__ Yl,
    const float* __restrict__ Xr, const float* __restrict__ Gr, float* __restrict__ Yr,
    int ldY, float* __restrict__ hfl, float* __restrict__ hfr) {
    const int gid = blockIdx.x * blockDim.x + threadIdx.x;  // 0..8191
    const int b = gid >> 8, f = gid & 255;

    // select direction (uniform per block)
    const float* __restrict__ X;
    const float* __restrict__ G;
    float* __restrict__ Y;
    float* __restrict__ hf;
    int xi, yi, sx, sy;
    if (blockIdx.y == 0) {           // left-to-right: t ascending
        X = Xl; G = Gl; Y = Yl; hf = hfl;
        xi = b * SEQ * H + f;                    sx = H;
        yi = b * SEQ * ldY + f;                  sy = ldY;
    } else {                          // right-to-left: t descending
        X = Xr; G = Gr; Y = Yr; hf = hfr;
        xi = b * SEQ * H + (SEQ - 1) * H + f;    sx = -H;
        yi = b * SEQ * ldY + (SEQ - 1) * ldY + f; sy = -ldY;
    }

    float h = 0.f;
    float xb[PF], gb[PF];
#pragma unroll
    for (int i = 0; i < PF; i++) {
        xb[i] = X[xi + i * sx];  gb[i] = G[xi + i * sx];
    }
    int p = xi + PF * sx;

    constexpr int NB = SEQ / PF;
#pragma unroll 1
    for (int blk = 0; blk < NB - 1; blk++) {
#pragma unroll
        for (int j = 0; j < PF; j++) {
            float x = xb[j], g = gb[j];
            // refill (unconditional; last block peeled)
            xb[j] = X[p + j * sx];  gb[j] = G[p + j * sx];
            // off-critical-path precompute
            float q  = fmaf(-g, x, x);      // x*(1-g)
            float xk = x * C2LOG2E;
            // serial chain
            float r = fmaf(g, h, q);
            float e = ex2f(xk * r);
            h = fmaf(-2.f, rcpf(e + 1.f), 1.f);
            Y[yi] = h;  yi += sy;
        }
        p += PF * sx;
    }
    // final block: consume only
#pragma unroll
    for (int j = 0; j < PF; j++) {
        float x = xb[j], g = gb[j];
        float q  = fmaf(-g, x, x);
        float xk = x * C2LOG2E;
        float r = fmaf(g, h, q);
        float e = ex2f(xk * r);
        h = fmaf(-2.f, rcpf(e + 1.f), 1.f);
        Y[yi] = h;  yi += sy;
    }
    hf[gid] = h;
}

// ---------------- launch ----------------------------------------------------
extern "C" void kernel_launch(void* const* d_in, const int* in_sizes, int n_in,
                              void* d_out, int out_size) {
    const float* x    = (const float*)d_in[0];
    const float* W_fc = (const float*)d_in[1];
    const float* b_fc = (const float*)d_in[2];
    // d_in[3]=W1, d_in[4]=b1 are mathematically dead (blending1 == identity)
    const float* W2   = (const float*)d_in[5];
    const float* b2   = (const float*)d_in[6];
    float* out = (float*)d_out;

    static float *pH1 = nullptr, *pG0 = nullptr, *pY0 = nullptr, *pG1 = nullptr, *pWr = nullptr;
    static bool inited = false;
    if (!inited) {
        cudaGetSymbolAddress((void**)&pH1, g_H1);
        cudaGetSymbolAddress((void**)&pG0, g_G0);
        cudaGetSymbolAddress((void**)&pY0, g_Y0);
        cudaGetSymbolAddress((void**)&pG1, g_G1);
        cudaGetSymbolAddress((void**)&pWr, g_Wr);
        cudaFuncSetAttribute(gemm_kernel<0>, cudaFuncAttributeMaxDynamicSharedMemorySize, GEMM_SMEM);
        cudaFuncSetAttribute(gemm_kernel<1>, cudaFuncAttributeMaxDynamicSharedMemorySize, GEMM_SMEM);
        inited = true;
    }

    float* ho = out + XXSZ;  // h_out section: 4 slots of [32,256]
    const float* Wfc_r = pWr;
    const float* W2_r  = pWr + WFC_N;

    // 0) pre-round weights to tf32 (bitwise identical to per-use cvt.rna)
    round_w_kernel<<<(WFC_N + W2_N + 255) / 256, 256>>>(W_fc, W2, pWr);
    // 1) input projection: H1 = x @ W_fc^T + b_fc           [65536,512]x[256,512]
    gemm_kernel<0><<<dim3(M0 / TBM, 2), 256, GEMM_SMEM>>>(x, Wfc_r, b_fc, pH1, M0, IN);
    // 2) layer-0 gates (shared by both directions): G0 = sigmoid(H1 @ W2_0^T + b2_0)
    gemm_kernel<1><<<dim3(M0 / TBM, 2), 256, GEMM_SMEM>>>(pH1, W2_r, b2, pG0, M0, H);
    // 3) layer-0 bidirectional scan -> Y0 (ltr half, rtl half in original t order)
    scan_dir_kernel<<<dim3(128, 2), 64>>>(pH1, pG0, pY0,
                                          pH1, pG0, pY0 + M0 * H,
                                          H, ho, ho + BS * H);
    // 4) layer-1 gates over both halves at once: G1 = sigmoid(Y0 @ W2_1^T + b2_1)
    gemm_kernel<1><<<dim3(2 * M0 / TBM, 2), 256, GEMM_SMEM>>>(pY0, W2_r + H * H, b2 + H, pG1, 2 * M0, H);
    // 5) layer-1 scan writing straight into d_out's [b,t,2H] layout + h_out
    scan_dir_kernel<<<dim3(128, 2), 64>>>(pY0, pG1, out,
                                          pY0 + M0 * H, pG1 + M0 * H, out + H,
                                          2 * H, ho + 2 * BS * H, ho + 3 * BS * H);
}

// round 10
// speedup vs baseline: 1.2829x; 1.2829x over previous
#include <cuda_runtime.h>
#include <cuda_bf16.h>
#include <cstdint>

// Problem dims
constexpr int BS  = 32;
constexpr int SEQ = 2048;
constexpr int IN  = 512;
constexpr int H   = 256;
constexpr int M0  = BS * SEQ;          // 65536 rows
constexpr int XXSZ = BS * SEQ * 2 * H; // 33554432 floats (xx output)

constexpr int WFC_N = H * IN;          // 131072
constexpr int W2_N  = 2 * H * H;       // 131072

// ---------------- scratch (device globals; no allocation allowed) -----------
__device__ float g_H1[M0 * H];       // input projection  (64 MB)
__device__ float g_G0[M0 * H];       // layer-0 gates     (64 MB)
__device__ float g_Y0[2 * M0 * H];   // layer-0 outputs, ltr then rtl (128 MB)
__device__ float g_G1[2 * M0 * H];   // layer-1 gates     (128 MB)
__device__ float g_Wr[WFC_N + W2_N]; // tf32-prerounded weights (1 MB)

// ---------------- small helpers ---------------------------------------------
__device__ __forceinline__ uint32_t f2tf(float x) {
    uint32_t u;
    asm("cvt.rna.tf32.f32 %0, %1;" : "=r"(u) : "f"(x));
    return u;
}

__device__ __forceinline__ void cp16(float* s, const float* g) {
    uint32_t sa = (uint32_t)__cvta_generic_to_shared(s);
    asm volatile("cp.async.cg.shared.global [%0], [%1], 16;\n" :: "r"(sa), "l"(g));
}
__device__ __forceinline__ void cp_commit() {
    asm volatile("cp.async.commit_group;\n" ::: "memory");
}
__device__ __forceinline__ void cp_wait1() {
    asm volatile("cp.async.wait_group 1;\n" ::: "memory");
}
__device__ __forceinline__ void cp_wait0() {
    asm volatile("cp.async.wait_group 0;\n" ::: "memory");
}

__device__ __forceinline__ void mma_tf32(float c[4], const uint32_t a[4], const uint32_t b[2]) {
    asm volatile(
        "mma.sync.aligned.m16n8k8.row.col.f32.tf32.tf32.f32 "
        "{%0,%1,%2,%3}, {%4,%5,%6,%7}, {%8,%9}, {%0,%1,%2,%3};\n"
        : "+f"(c[0]), "+f"(c[1]), "+f"(c[2]), "+f"(c[3])
        : "r"(a[0]), "r"(a[1]), "r"(a[2]), "r"(a[3]), "r"(b[0]), "r"(b[1]));
}

// accurate-enough tanh pieces: ex2.approx + rcp.approx (rel err ~1e-6)
__device__ __forceinline__ float ex2f(float z) {
    float e; asm("ex2.approx.f32 %0, %1;" : "=f"(e) : "f"(z)); return e;
}
__device__ __forceinline__ float rcpf(float d) {
    float r; asm("rcp.approx.f32 %0, %1;" : "=f"(r) : "f"(d)); return r;
}

// ---------------- weight pre-round to tf32 (bitwise == cvt.rna per use) -----
__global__ void round_w_kernel(const float* __restrict__ Wfc,
                               const float* __restrict__ W2,
                               float* __restrict__ out) {
    int i = blockIdx.x * blockDim.x + threadIdx.x;
    if (i < WFC_N) {
        out[i] = __uint_as_float(f2tf(Wfc[i]));
    } else if (i < WFC_N + W2_N) {
        out[i] = __uint_as_float(f2tf(W2[i - WFC_N]));
    }
}

// ---------------- GEMM: C[M,256] = act(A[M,K] @ W[256,K]^T + bias) ----------
// tiles: 128x128x32, 256 threads = 8 warps laid out 4(m) x 2(n),
// warp tile 32x64. W is pre-rounded tf32 -> B frags need no cvt.
constexpr int TBM = 128, TBN = 128, TBK = 32, LDT = 36;
constexpr int GEMM_SMEM = 2 * 2 * TBM * LDT * (int)sizeof(float);  // 73728 B

template <int ACT>
__launch_bounds__(256, 2)
__global__ void gemm_kernel(const float* __restrict__ A, const float* __restrict__ W,
                            const float* __restrict__ bias, float* __restrict__ C,
                            int M, int K) {
    extern __shared__ float smem[];
    float* As = smem;                 // [2][128][36]
    float* Bs = smem + 2 * TBM * LDT; // [2][128][36]

    const int tid  = threadIdx.x;
    const int warp = tid >> 5, lane = tid & 31;
    const int wm = (warp >> 1) * 32;   // 4 distinct m-slabs (A redundancy 2x)
    const int wn = (warp & 1) * 64;    // 2 distinct n-slabs
    const int bm = blockIdx.x * TBM;
    const int bn = blockIdx.y * TBN;

    float acc[2][8][4];
#pragma unroll
    for (int i = 0; i < 2; i++)
#pragma unroll
        for (int j = 0; j < 8; j++)
#pragma unroll
            for (int k = 0; k < 4; k++) acc[i][j][k] = 0.f;

    auto load_tile = [&](int kt, int buf) {
        const float* Ag = A + bm * K + kt * TBK;
        const float* Wg = W + bn * K + kt * TBK;
        float* Asb = As + buf * TBM * LDT;
        float* Bsb = Bs + buf * TBM * LDT;
#pragma unroll
        for (int i = 0; i < 4; i++) {
            int idx = i * 256 + tid;
            int row = idx >> 3, c4 = (idx & 7) * 4;
            cp16(Asb + row * LDT + c4, Ag + row * K + c4);
            cp16(Bsb + row * LDT + c4, Wg + row * K + c4);
        }
    };

    const int KT = K / TBK;
    load_tile(0, 0);
    cp_commit();

    for (int kt = 0; kt < KT; kt++) {
        const int cur = kt & 1;
        if (kt + 1 < KT) {
            load_tile(kt + 1, cur ^ 1);
            cp_commit();
            cp_wait1();
        } else {
            cp_wait0();
        }
        __syncthreads();

        const float* __restrict__ Asb = As + cur * TBM * LDT;
        const float* __restrict__ Bsb = Bs + cur * TBM * LDT;
        const int r0 = wm + (lane >> 2);
        const int kc = lane & 3;
#pragma unroll
        for (int kk = 0; kk < 4; kk++) {
            uint32_t a[2][4], b[8][2];
#pragma unroll
            for (int mi = 0; mi < 2; mi++) {
                int r = r0 + mi * 16;
                a[mi][0] = f2tf(Asb[r * LDT + kk * 8 + kc]);
                a[mi][1] = f2tf(Asb[(r + 8) * LDT + kk * 8 + kc]);
                a[mi][2] = f2tf(Asb[r * LDT + kk * 8 + kc + 4]);
                a[mi][3] = f2tf(Asb[(r + 8) * LDT + kk * 8 + kc + 4]);
            }
#pragma unroll
            for (int ni = 0; ni < 8; ni++) {
                int n = wn + ni * 8 + (lane >> 2);
                // weights pre-rounded to tf32: raw bits are already canonical
                b[ni][0] = __float_as_uint(Bsb[n * LDT + kk * 8 + kc]);
                b[ni][1] = __float_as_uint(Bsb[n * LDT + kk * 8 + kc + 4]);
            }
#pragma unroll
            for (int mi = 0; mi < 2; mi++)
#pragma unroll
                for (int ni = 0; ni < 8; ni++) mma_tf32(acc[mi][ni], a[mi], b[ni]);
        }
        __syncthreads();
    }

    // epilogue: bias (+ sigmoid)
#pragma unroll
    for (int mi = 0; mi < 2; mi++) {
        int row = bm + wm + mi * 16 + (lane >> 2);
#pragma unroll
        for (int ni = 0; ni < 8; ni++) {
            int col = bn + wn + ni * 8 + (lane & 3) * 2;
            float b0 = bias[col], b1 = bias[col + 1];
            float v0 = acc[mi][ni][0] + b0;
            float v1 = acc[mi][ni][1] + b1;
            float v2 = acc[mi][ni][2] + b0;
            float v3 = acc[mi][ni][3] + b1;
            if (ACT) {
                v0 = 1.f / (1.f + __expf(-v0));
                v1 = 1.f / (1.f + __expf(-v1));
                v2 = 1.f / (1.f + __expf(-v2));
                v3 = 1.f / (1.f + __expf(-v3));
            }
            *(float2*)(C + row * 256 + col)       = make_float2(v0, v1);
            *(float2*)(C + (row + 8) * 256 + col) = make_float2(v2, v3);
        }
    }
}

// ---------------- bidirectional scan, one direction per thread --------------
// 16384 independent chains (8192 (b,f) pairs x 2 directions); blockIdx.y picks
// the direction, templated so strides are compile-time immediates.
// Chain: fma -> mul -> ex2 -> add -> rcp -> fma  (~48 cyc/step floor).
// 16-deep register prefetch (16*48 = 768 cyc window > DRAM ~600); last block
// peeled. NO register cap: the round-9 __launch_bounds__(64,16) clamp forced
// 64 regs and spilled the prefetch arrays to local (228 cyc/step observed).
constexpr int PF = 16;
constexpr float C2LOG2E = 2.8853900817779268f;  // 2*log2(e)

template <int DT, int LDY>   // DT = +1 (ltr) or -1 (rtl); LDY = output stride
__device__ __forceinline__ void scan_impl(
    const float* __restrict__ X, const float* __restrict__ G,
    float* __restrict__ Y, float* __restrict__ hf, int gid) {
    const int b = gid >> 8, f = gid & 255;
    constexpr int T0 = (DT > 0) ? 0 : (SEQ - 1);
    constexpr int XS = DT * H;      // compile-time immediates
    constexpr int YS = DT * LDY;

    int xi = b * SEQ * H + T0 * H + f;
    int yi = b * SEQ * LDY + T0 * LDY + f;

    float h = 0.f;
    float xb[PF], gb[PF];
#pragma unroll
    for (int i = 0; i < PF; i++) {
        xb[i] = X[xi + i * XS];  gb[i] = G[xi + i * XS];
    }
    int p = xi + PF * XS;

    constexpr int NB = SEQ / PF;
#pragma unroll 1
    for (int blk = 0; blk < NB - 1; blk++) {
#pragma unroll
        for (int j = 0; j < PF; j++) {
            float x = xb[j], g = gb[j];
            // refill (unconditional; last block peeled)
            xb[j] = X[p + j * XS];  gb[j] = G[p + j * XS];
            // off-critical-path precompute
            float q  = fmaf(-g, x, x);      // x*(1-g)
            float xk = x * C2LOG2E;
            // serial chain
            float r = fmaf(g, h, q);
            float e = ex2f(xk * r);
            h = fmaf(-2.f, rcpf(e + 1.f), 1.f);
            Y[yi] = h;  yi += YS;
        }
        p += PF * XS;
    }
    // final block: consume only
#pragma unroll
    for (int j = 0; j < PF; j++) {
        float x = xb[j], g = gb[j];
        float q  = fmaf(-g, x, x);
        float xk = x * C2LOG2E;
        float r = fmaf(g, h, q);
        float e = ex2f(xk * r);
        h = fmaf(-2.f, rcpf(e + 1.f), 1.f);
        Y[yi] = h;  yi += YS;
    }
    hf[gid] = h;
}

template <int LDY>
__global__ void scan_kernel(
    const float* __restrict__ Xl, const float* __restrict__ Gl,
    float* __restrict__ Yl, float* __restrict__ hfl,
    const float* __restrict__ Xr, const float* __restrict__ Gr,
    float* __restrict__ Yr, float* __restrict__ hfr) {
    const int gid = blockIdx.x * blockDim.x + threadIdx.x;  // 0..8191
    if (blockIdx.y == 0)
        scan_impl<+1, LDY>(Xl, Gl, Yl, hfl, gid);
    else
        scan_impl<-1, LDY>(Xr, Gr, Yr, hfr, gid);
}

// ---------------- launch ----------------------------------------------------
extern "C" void kernel_launch(void* const* d_in, const int* in_sizes, int n_in,
                              void* d_out, int out_size) {
    const float* x    = (const float*)d_in[0];
    const float* W_fc = (const float*)d_in[1];
    const float* b_fc = (const float*)d_in[2];
    // d_in[3]=W1, d_in[4]=b1 are mathematically dead (blending1 == identity)
    const float* W2   = (const float*)d_in[5];
    const float* b2   = (const float*)d_in[6];
    float* out = (float*)d_out;

    static float *pH1 = nullptr, *pG0 = nullptr, *pY0 = nullptr, *pG1 = nullptr, *pWr = nullptr;
    static bool inited = false;
    if (!inited) {
        cudaGetSymbolAddress((void**)&pH1, g_H1);
        cudaGetSymbolAddress((void**)&pG0, g_G0);
        cudaGetSymbolAddress((void**)&pY0, g_Y0);
        cudaGetSymbolAddress((void**)&pG1, g_G1);
        cudaGetSymbolAddress((void**)&pWr, g_Wr);
        cudaFuncSetAttribute(gemm_kernel<0>, cudaFuncAttributeMaxDynamicSharedMemorySize, GEMM_SMEM);
        cudaFuncSetAttribute(gemm_kernel<1>, cudaFuncAttributeMaxDynamicSharedMemorySize, GEMM_SMEM);
        inited = true;
    }

    float* ho = out + XXSZ;  // h_out section: 4 slots of [32,256]
    const float* Wfc_r = pWr;
    const float* W2_r  = pWr + WFC_N;

    // 0) pre-round weights to tf32 (bitwise identical to per-use cvt.rna)
    round_w_kernel<<<(WFC_N + W2_N + 255) / 256, 256>>>(W_fc, W2, pWr);
    // 1) input projection: H1 = x @ W_fc^T + b_fc           [65536,512]x[256,512]
    gemm_kernel<0><<<dim3(M0 / TBM, 2), 256, GEMM_SMEM>>>(x, Wfc_r, b_fc, pH1, M0, IN);
    // 2) layer-0 gates (shared by both directions): G0 = sigmoid(H1 @ W2_0^T + b2_0)
    gemm_kernel<1><<<dim3(M0 / TBM, 2), 256, GEMM_SMEM>>>(pH1, W2_r, b2, pG0, M0, H);
    // 3) layer-0 bidirectional scan -> Y0 (ltr half, rtl half in original t order)
    scan_kernel<H><<<dim3(128, 2), 64>>>(pH1, pG0, pY0, ho,
                                         pH1, pG0, pY0 + M0 * H, ho + BS * H);
    // 4) layer-1 gates over both halves at once: G1 = sigmoid(Y0 @ W2_1^T + b2_1)
    gemm_kernel<1><<<dim3(2 * M0 / TBM, 2), 256, GEMM_SMEM>>>(pY0, W2_r + H * H, b2 + H, pG1, 2 * M0, H);
    // 5) layer-1 scan writing straight into d_out's [b,t,2H] layout + h_out
    scan_kernel<2 * H><<<dim3(128, 2), 64>>>(pY0, pG1, out, ho + 2 * BS * H,
                                             pY0 + M0 * H, pG1 + M0 * H, out + H, ho + 3 * BS * H);
}

// round 11
// speedup vs baseline: 1.5495x; 1.2078x over previous
#include <cuda_runtime.h>
#include <cuda_bf16.h>
#include <cstdint>

// Problem dims
constexpr int BS  = 32;
constexpr int SEQ = 2048;
constexpr int IN  = 512;
constexpr int H   = 256;
constexpr int M0  = BS * SEQ;          // 65536 rows
constexpr int XXSZ = BS * SEQ * 2 * H; // 33554432 floats (xx output)

constexpr int WFC_N = H * IN;          // 131072
constexpr int W2_N  = 2 * H * H;       // 131072

// ---------------- scratch (device globals; no allocation allowed) -----------
__device__ float g_H1[M0 * H];       // input projection  (64 MB)
__device__ float g_G0[M0 * H];       // layer-0 gates     (64 MB)
__device__ float g_Y0[2 * M0 * H];   // layer-0 outputs, ltr then rtl (128 MB)
__device__ float g_G1[2 * M0 * H];   // layer-1 gates     (128 MB)
__device__ float g_Wr[WFC_N + W2_N]; // tf32-prerounded weights (1 MB)

// ---------------- small helpers ---------------------------------------------
__device__ __forceinline__ uint32_t f2tf(float x) {
    uint32_t u;
    asm("cvt.rna.tf32.f32 %0, %1;" : "=r"(u) : "f"(x));
    return u;
}

__device__ __forceinline__ void cp16(void* s, const void* g) {
    uint32_t sa = (uint32_t)__cvta_generic_to_shared(s);
    asm volatile("cp.async.cg.shared.global [%0], [%1], 16;\n" :: "r"(sa), "l"(g));
}
__device__ __forceinline__ void cp_commit() {
    asm volatile("cp.async.commit_group;\n" ::: "memory");
}
__device__ __forceinline__ void cp_wait1() {
    asm volatile("cp.async.wait_group 1;\n" ::: "memory");
}
__device__ __forceinline__ void cp_wait0() {
    asm volatile("cp.async.wait_group 0;\n" ::: "memory");
}

__device__ __forceinline__ void mma_tf32(float c[4], const uint32_t a[4], const uint32_t b[2]) {
    asm volatile(
        "mma.sync.aligned.m16n8k8.row.col.f32.tf32.tf32.f32 "
        "{%0,%1,%2,%3}, {%4,%5,%6,%7}, {%8,%9}, {%0,%1,%2,%3};\n"
        : "+f"(c[0]), "+f"(c[1]), "+f"(c[2]), "+f"(c[3])
        : "r"(a[0]), "r"(a[1]), "r"(a[2]), "r"(a[3]), "r"(b[0]), "r"(b[1]));
}

// accurate-enough tanh pieces: ex2.approx + rcp.approx (rel err ~1e-6)
__device__ __forceinline__ float ex2f(float z) {
    float e; asm("ex2.approx.f32 %0, %1;" : "=f"(e) : "f"(z)); return e;
}
__device__ __forceinline__ float rcpf(float d) {
    float r; asm("rcp.approx.f32 %0, %1;" : "=f"(r) : "f"(d)); return r;
}

// ---------------- weight pre-round to tf32 (bitwise == cvt.rna per use) -----
__global__ void round_w_kernel(const float* __restrict__ Wfc,
                               const float* __restrict__ W2,
                               float* __restrict__ out) {
    int i = blockIdx.x * blockDim.x + threadIdx.x;
    if (i < WFC_N) {
        out[i] = __uint_as_float(f2tf(Wfc[i]));
    } else if (i < WFC_N + W2_N) {
        out[i] = __uint_as_float(f2tf(W2[i - WFC_N]));
    }
}

// ---------------- GEMM: C[M,256] = act(A[M,K] @ W[256,K]^T + bias) ----------
// tiles: 128x128x32, 256 threads = 8 warps laid out 4(m) x 2(n),
// warp tile 32x64. W is pre-rounded tf32 -> B frags need no cvt.
constexpr int TBM = 128, TBN = 128, TBK = 32, LDT = 36;
constexpr int GEMM_SMEM = 2 * 2 * TBM * LDT * (int)sizeof(float);  // 73728 B

template <int ACT>
__launch_bounds__(256, 2)
__global__ void gemm_kernel(const float* __restrict__ A, const float* __restrict__ W,
                            const float* __restrict__ bias, float* __restrict__ C,
                            int M, int K) {
    extern __shared__ float smem[];
    float* As = smem;                 // [2][128][36]
    float* Bs = smem + 2 * TBM * LDT; // [2][128][36]

    const int tid  = threadIdx.x;
    const int warp = tid >> 5, lane = tid & 31;
    const int wm = (warp >> 1) * 32;   // 4 distinct m-slabs (A redundancy 2x)
    const int wn = (warp & 1) * 64;    // 2 distinct n-slabs
    const int bm = blockIdx.x * TBM;
    const int bn = blockIdx.y * TBN;

    float acc[2][8][4];
#pragma unroll
    for (int i = 0; i < 2; i++)
#pragma unroll
        for (int j = 0; j < 8; j++)
#pragma unroll
            for (int k = 0; k < 4; k++) acc[i][j][k] = 0.f;

    auto load_tile = [&](int kt, int buf) {
        const float* Ag = A + bm * K + kt * TBK;
        const float* Wg = W + bn * K + kt * TBK;
        float* Asb = As + buf * TBM * LDT;
        float* Bsb = Bs + buf * TBM * LDT;
#pragma unroll
        for (int i = 0; i < 4; i++) {
            int idx = i * 256 + tid;
            int row = idx >> 3, c4 = (idx & 7) * 4;
            cp16(Asb + row * LDT + c4, Ag + row * K + c4);
            cp16(Bsb + row * LDT + c4, Wg + row * K + c4);
        }
    };

    const int KT = K / TBK;
    load_tile(0, 0);
    cp_commit();

    for (int kt = 0; kt < KT; kt++) {
        const int cur = kt & 1;
        if (kt + 1 < KT) {
            load_tile(kt + 1, cur ^ 1);
            cp_commit();
            cp_wait1();
        } else {
            cp_wait0();
        }
        __syncthreads();

        const float* __restrict__ Asb = As + cur * TBM * LDT;
        const float* __restrict__ Bsb = Bs + cur * TBM * LDT;
        const int r0 = wm + (lane >> 2);
        const int kc = lane & 3;
#pragma unroll
        for (int kk = 0; kk < 4; kk++) {
            uint32_t a[2][4], b[8][2];
#pragma unroll
            for (int mi = 0; mi < 2; mi++) {
                int r = r0 + mi * 16;
                a[mi][0] = f2tf(Asb[r * LDT + kk * 8 + kc]);
                a[mi][1] = f2tf(Asb[(r + 8) * LDT + kk * 8 + kc]);
                a[mi][2] = f2tf(Asb[r * LDT + kk * 8 + kc + 4]);
                a[mi][3] = f2tf(Asb[(r + 8) * LDT + kk * 8 + kc + 4]);
            }
#pragma unroll
            for (int ni = 0; ni < 8; ni++) {
                int n = wn + ni * 8 + (lane >> 2);
                // weights pre-rounded to tf32: raw bits are already canonical
                b[ni][0] = __float_as_uint(Bsb[n * LDT + kk * 8 + kc]);
                b[ni][1] = __float_as_uint(Bsb[n * LDT + kk * 8 + kc + 4]);
            }
#pragma unroll
            for (int mi = 0; mi < 2; mi++)
#pragma unroll
                for (int ni = 0; ni < 8; ni++) mma_tf32(acc[mi][ni], a[mi], b[ni]);
        }
        __syncthreads();
    }

    // epilogue: bias (+ sigmoid)
#pragma unroll
    for (int mi = 0; mi < 2; mi++) {
        int row = bm + wm + mi * 16 + (lane >> 2);
#pragma unroll
        for (int ni = 0; ni < 8; ni++) {
            int col = bn + wn + ni * 8 + (lane & 3) * 2;
            float b0 = bias[col], b1 = bias[col + 1];
            float v0 = acc[mi][ni][0] + b0;
            float v1 = acc[mi][ni][1] + b1;
            float v2 = acc[mi][ni][2] + b0;
            float v3 = acc[mi][ni][3] + b1;
            if (ACT) {
                v0 = 1.f / (1.f + __expf(-v0));
                v1 = 1.f / (1.f + __expf(-v1));
                v2 = 1.f / (1.f + __expf(-v2));
                v3 = 1.f / (1.f + __expf(-v3));
            }
            *(float2*)(C + row * 256 + col)       = make_float2(v0, v1);
            *(float2*)(C + (row + 8) * 256 + col) = make_float2(v2, v3);
        }
    }
}

// ---------------- bidirectional scan with cp.async smem staging -------------
// Block = 64 threads = 64 chains (one f-group of one batch, one direction).
// x/g for CH=16 timesteps are staged into smem via cp.async (double-buffered);
// one wait_group per stage lands on data requested 16 steps (~800 cyc) earlier,
// so the recurrence chain (fma->mul->ex2->add->rcp->fma, ~48 cyc/step) reads
// only smem (LDS, prefetched 1 step ahead) and never waits on DRAM.
constexpr int CH = 16;
constexpr float C2LOG2E = 2.8853900817779268f;  // 2*log2(e)

template <int DT, int LDY>   // DT = +1 (ltr) or -1 (rtl); LDY = output stride
__device__ __forceinline__ void scan_impl(
    const float* __restrict__ X, const float* __restrict__ G,
    float* __restrict__ Y, float* __restrict__ hf) {
    __shared__ float sX[2][CH][64];
    __shared__ float sG[2][CH][64];

    const int tid = threadIdx.x;
    const int b  = blockIdx.x >> 2;      // batch
    const int fg = blockIdx.x & 3;       // feature group (64 wide)
    const int f  = fg * 64 + tid;
    constexpr int T0 = (DT > 0) ? 0 : (SEQ - 1);
    constexpr int YS = DT * LDY;

    const float* Xb = X + b * SEQ * H + T0 * H + fg * 64;
    const float* Gb = G + b * SEQ * H + T0 * H + fg * 64;
    int yi = b * SEQ * LDY + T0 * LDY + f;

    const int lr = tid >> 4;          // row sub-index within a round (0..3)
    const int lc = (tid & 15) * 4;    // float column (16B aligned)

    auto stage = [&](int s, int buf) {
#pragma unroll
        for (int r = 0; r < 4; r++) {
            int row = r * 4 + lr;                        // timestep within stage
            int off = DT * (s * CH + row) * H + lc;
            cp16(&sX[buf][row][lc], Xb + off);
            cp16(&sG[buf][row][lc], Gb + off);
        }
        cp_commit();
    };

    stage(0, 0);
    stage(1, 1);

    float h = 0.f;
    constexpr int NB = SEQ / CH;  // 128
#pragma unroll 1
    for (int s = 0; s < NB; s++) {
        const int buf = s & 1;
        if (s == NB - 1) cp_wait0(); else cp_wait1();
        __syncthreads();   // make all threads' cp.async data visible

        float xr = sX[buf][0][tid], gr = sG[buf][0][tid];
#pragma unroll
        for (int j = 0; j < CH; j++) {
            float x = xr, g = gr;
            if (j + 1 < CH) { xr = sX[buf][j + 1][tid]; gr = sG[buf][j + 1][tid]; }
            // off-critical-path precompute
            float q  = fmaf(-g, x, x);      // x*(1-g)
            float xk = x * C2LOG2E;
            // serial chain
            float r = fmaf(g, h, q);
            float e = ex2f(xk * r);
            h = fmaf(-2.f, rcpf(e + 1.f), 1.f);
            Y[yi] = h;  yi += YS;
        }
        __syncthreads();   // all reads of buf done before refill overwrites it
        if (s + 2 < NB) stage(s + 2, buf);
    }
    hf[b * 256 + f] = h;
}

template <int LDY>
__launch_bounds__(64)
__global__ void scan_kernel(
    const float* __restrict__ Xl, const float* __restrict__ Gl,
    float* __restrict__ Yl, float* __restrict__ hfl,
    const float* __restrict__ Xr, const float* __restrict__ Gr,
    float* __restrict__ Yr, float* __restrict__ hfr) {
    if (blockIdx.y == 0)
        scan_impl<+1, LDY>(Xl, Gl, Yl, hfl);
    else
        scan_impl<-1, LDY>(Xr, Gr, Yr, hfr);
}

// ---------------- launch ----------------------------------------------------
extern "C" void kernel_launch(void* const* d_in, const int* in_sizes, int n_in,
                              void* d_out, int out_size) {
    const float* x    = (const float*)d_in[0];
    const float* W_fc = (const float*)d_in[1];
    const float* b_fc = (const float*)d_in[2];
    // d_in[3]=W1, d_in[4]=b1 are mathematically dead (blending1 == identity)
    const float* W2   = (const float*)d_in[5];
    const float* b2   = (const float*)d_in[6];
    float* out = (float*)d_out;

    static float *pH1 = nullptr, *pG0 = nullptr, *pY0 = nullptr, *pG1 = nullptr, *pWr = nullptr;
    static bool inited = false;
    if (!inited) {
        cudaGetSymbolAddress((void**)&pH1, g_H1);
        cudaGetSymbolAddress((void**)&pG0, g_G0);
        cudaGetSymbolAddress((void**)&pY0, g_Y0);
        cudaGetSymbolAddress((void**)&pG1, g_G1);
        cudaGetSymbolAddress((void**)&pWr, g_Wr);
        cudaFuncSetAttribute(gemm_kernel<0>, cudaFuncAttributeMaxDynamicSharedMemorySize, GEMM_SMEM);
        cudaFuncSetAttribute(gemm_kernel<1>, cudaFuncAttributeMaxDynamicSharedMemorySize, GEMM_SMEM);
        inited = true;
    }

    float* ho = out + XXSZ;  // h_out section: 4 slots of [32,256]
    const float* Wfc_r = pWr;
    const float* W2_r  = pWr + WFC_N;

    // 0) pre-round weights to tf32 (bitwise identical to per-use cvt.rna)
    round_w_kernel<<<(WFC_N + W2_N + 255) / 256, 256>>>(W_fc, W2, pWr);
    // 1) input projection: H1 = x @ W_fc^T + b_fc           [65536,512]x[256,512]
    gemm_kernel<0><<<dim3(M0 / TBM, 2), 256, GEMM_SMEM>>>(x, Wfc_r, b_fc, pH1, M0, IN);
    // 2) layer-0 gates (shared by both directions): G0 = sigmoid(H1 @ W2_0^T + b2_0)
    gemm_kernel<1><<<dim3(M0 / TBM, 2), 256, GEMM_SMEM>>>(pH1, W2_r, b2, pG0, M0, H);
    // 3) layer-0 bidirectional scan -> Y0 (ltr half, rtl half in original t order)
    scan_kernel<H><<<dim3(128, 2), 64>>>(pH1, pG0, pY0, ho,
                                         pH1, pG0, pY0 + M0 * H, ho + BS * H);
    // 4) layer-1 gates over both halves at once: G1 = sigmoid(Y0 @ W2_1^T + b2_1)
    gemm_kernel<1><<<dim3(2 * M0 / TBM, 2), 256, GEMM_SMEM>>>(pY0, W2_r + H * H, b2 + H, pG1, 2 * M0, H);
    // 5) layer-1 scan writing straight into d_out's [b,t,2H] layout + h_out
    scan_kernel<2 * H><<<dim3(128, 2), 64>>>(pY0, pG1, out, ho + 2 * BS * H,
                                             pY0 + M0 * H, pG1 + M0 * H, out + H, ho + 3 * BS * H);
}

// round 13
// speedup vs baseline: 1.6925x; 1.0923x over previous
#include <cuda_runtime.h>
#include <cuda_bf16.h>
#include <cstdint>

// Problem dims
constexpr int BS  = 32;
constexpr int SEQ = 2048;
constexpr int IN  = 512;
constexpr int H   = 256;
constexpr int M0  = BS * SEQ;          // 65536 rows
constexpr int XXSZ = BS * SEQ * 2 * H; // 33554432 floats (xx output)

constexpr int WFC_N = H * IN;          // 131072
constexpr int W2_N  = 2 * H * H;       // 131072

// ---------------- scratch (device globals; no allocation allowed) -----------
__device__ float g_H1[M0 * H];       // input projection  (64 MB)
__device__ float g_G0[M0 * H];       // layer-0 gates     (64 MB)
__device__ float g_Y0[2 * M0 * H];   // layer-0 outputs, ltr then rtl (128 MB)
__device__ float g_G1[2 * M0 * H];   // layer-1 gates     (128 MB)
__device__ float g_Wr[WFC_N + W2_N]; // tf32-prerounded weights (1 MB)

// ---------------- small helpers ---------------------------------------------
__device__ __forceinline__ uint32_t f2tf(float x) {
    uint32_t u;
    asm("cvt.rna.tf32.f32 %0, %1;" : "=r"(u) : "f"(x));
    return u;
}

__device__ __forceinline__ void cp16(void* s, const void* g) {
    uint32_t sa = (uint32_t)__cvta_generic_to_shared(s);
    asm volatile("cp.async.cg.shared.global [%0], [%1], 16;\n" :: "r"(sa), "l"(g));
}
__device__ __forceinline__ void cp_commit() {
    asm volatile("cp.async.commit_group;\n" ::: "memory");
}
__device__ __forceinline__ void cp_wait1() {
    asm volatile("cp.async.wait_group 1;\n" ::: "memory");
}
__device__ __forceinline__ void cp_wait0() {
    asm volatile("cp.async.wait_group 0;\n" ::: "memory");
}

__device__ __forceinline__ void mma_tf32(float c[4], const uint32_t a[4], const uint32_t b[2]) {
    asm volatile(
        "mma.sync.aligned.m16n8k8.row.col.f32.tf32.tf32.f32 "
        "{%0,%1,%2,%3}, {%4,%5,%6,%7}, {%8,%9}, {%0,%1,%2,%3};\n"
        : "+f"(c[0]), "+f"(c[1]), "+f"(c[2]), "+f"(c[3])
        : "r"(a[0]), "r"(a[1]), "r"(a[2]), "r"(a[3]), "r"(b[0]), "r"(b[1]));
}

// MUFU tanh (Turing+): single 16-cyc op
__device__ __forceinline__ float tanh_a(float p) {
    float o; asm("tanh.approx.f32 %0, %1;" : "=f"(o) : "f"(p)); return o;
}

// ---------------- weight pre-round to tf32 (bitwise == cvt.rna per use) -----
__global__ void round_w_kernel(const float* __restrict__ Wfc,
                               const float* __restrict__ W2,
                               float* __restrict__ out) {
    int i = blockIdx.x * blockDim.x + threadIdx.x;
    if (i < WFC_N) {
        out[i] = __uint_as_float(f2tf(Wfc[i]));
    } else if (i < WFC_N + W2_N) {
        out[i] = __uint_as_float(f2tf(W2[i - WFC_N]));
    }
}

// ---------------- GEMM: C[M,256] = act(A[M,K] @ W[256,K]^T + bias) ----------
// tiles: 128x128x32, 256 threads = 8 warps laid out 4(m) x 2(n),
// warp tile 32x64. W is pre-rounded tf32 -> B frags need no cvt.
constexpr int TBM = 128, TBN = 128, TBK = 32, LDT = 36;
constexpr int GEMM_SMEM = 2 * 2 * TBM * LDT * (int)sizeof(float);  // 73728 B

template <int ACT>
__launch_bounds__(256, 2)
__global__ void gemm_kernel(const float* __restrict__ A, const float* __restrict__ W,
                            const float* __restrict__ bias, float* __restrict__ C,
                            int M, int K) {
    extern __shared__ float smem[];
    float* As = smem;                 // [2][128][36]
    float* Bs = smem + 2 * TBM * LDT; // [2][128][36]

    const int tid  = threadIdx.x;
    const int warp = tid >> 5, lane = tid & 31;
    const int wm = (warp >> 1) * 32;   // 4 distinct m-slabs (A redundancy 2x)
    const int wn = (warp & 1) * 64;    // 2 distinct n-slabs
    const int bm = blockIdx.x * TBM;
    const int bn = blockIdx.y * TBN;

    float acc[2][8][4];
#pragma unroll
    for (int i = 0; i < 2; i++)
#pragma unroll
        for (int j = 0; j < 8; j++)
#pragma unroll
            for (int k = 0; k < 4; k++) acc[i][j][k] = 0.f;

    auto load_tile = [&](int kt, int buf) {
        const float* Ag = A + bm * K + kt * TBK;
        const float* Wg = W + bn * K + kt * TBK;
        float* Asb = As + buf * TBM * LDT;
        float* Bsb = Bs + buf * TBM * LDT;
#pragma unroll
        for (int i = 0; i < 4; i++) {
            int idx = i * 256 + tid;
            int row = idx >> 3, c4 = (idx & 7) * 4;
            cp16(Asb + row * LDT + c4, Ag + row * K + c4);
            cp16(Bsb + row * LDT + c4, Wg + row * K + c4);
        }
    };

    const int KT = K / TBK;
    load_tile(0, 0);
    cp_commit();

    for (int kt = 0; kt < KT; kt++) {
        const int cur = kt & 1;
        if (kt + 1 < KT) {
            load_tile(kt + 1, cur ^ 1);
            cp_commit();
            cp_wait1();
        } else {
            cp_wait0();
        }
        __syncthreads();

        const float* __restrict__ Asb = As + cur * TBM * LDT;
        const float* __restrict__ Bsb = Bs + cur * TBM * LDT;
        const int r0 = wm + (lane >> 2);
        const int kc = lane & 3;
#pragma unroll
        for (int kk = 0; kk < 4; kk++) {
            uint32_t a[2][4], b[8][2];
#pragma unroll
            for (int mi = 0; mi < 2; mi++) {
                int r = r0 + mi * 16;
                a[mi][0] = f2tf(Asb[r * LDT + kk * 8 + kc]);
                a[mi][1] = f2tf(Asb[(r + 8) * LDT + kk * 8 + kc]);
                a[mi][2] = f2tf(Asb[r * LDT + kk * 8 + kc + 4]);
                a[mi][3] = f2tf(Asb[(r + 8) * LDT + kk * 8 + kc + 4]);
            }
#pragma unroll
            for (int ni = 0; ni < 8; ni++) {
                int n = wn + ni * 8 + (lane >> 2);
                // weights pre-rounded to tf32: raw bits are already canonical
                b[ni][0] = __float_as_uint(Bsb[n * LDT + kk * 8 + kc]);
                b[ni][1] = __float_as_uint(Bsb[n * LDT + kk * 8 + kc + 4]);
            }
#pragma unroll
            for (int mi = 0; mi < 2; mi++)
#pragma unroll
                for (int ni = 0; ni < 8; ni++) mma_tf32(acc[mi][ni], a[mi], b[ni]);
        }
        __syncthreads();
    }

    // epilogue: bias (+ sigmoid)
#pragma unroll
    for (int mi = 0; mi < 2; mi++) {
        int row = bm + wm + mi * 16 + (lane >> 2);
#pragma unroll
        for (int ni = 0; ni < 8; ni++) {
            int col = bn + wn + ni * 8 + (lane & 3) * 2;
            float b0 = bias[col], b1 = bias[col + 1];
            float v0 = acc[mi][ni][0] + b0;
            float v1 = acc[mi][ni][1] + b1;
            float v2 = acc[mi][ni][2] + b0;
            float v3 = acc[mi][ni][3] + b1;
            if (ACT) {
                v0 = 1.f / (1.f + __expf(-v0));
                v1 = 1.f / (1.f + __expf(-v1));
                v2 = 1.f / (1.f + __expf(-v2));
                v3 = 1.f / (1.f + __expf(-v3));
            }
            *(float2*)(C + row * 256 + col)       = make_float2(v0, v1);
            *(float2*)(C + (row + 8) * 256 + col) = make_float2(v2, v3);
        }
    }
}

// ---------------- bidirectional scan: both directions per thread ------------
// h_{t+1} = tanh(xg·h_t + xq), xg = x·g, xq = x^2(1-g) precomputed off-chain
// from cp.async-staged smem. Chain per direction = fma(4) + MUFU tanh(16) =
// 20 cyc; the ltr and rtl chains interleave in one thread and hide each
// other's latency. Grid = 128 blocks = one clean wave on 148 SMs.
constexpr int CH = 16;

template <int LDY>   // output row stride (H for layer 0, 2H for layer 1)
__launch_bounds__(64)
__global__ void scan_bi_kernel(
    const float* __restrict__ X1, const float* __restrict__ G1,
    float* __restrict__ Y1, float* __restrict__ hf1,   // ltr stream
    const float* __restrict__ X2, const float* __restrict__ G2,
    float* __restrict__ Y2, float* __restrict__ hf2) { // rtl stream
    __shared__ float sXl[2][CH][64], sGl[2][CH][64];
    __shared__ float sXr[2][CH][64], sGr[2][CH][64];   // 16 KB total

    const int tid = threadIdx.x;
    const int b  = blockIdx.x >> 2;      // batch
    const int fg = blockIdx.x & 3;       // feature group (64 wide)
    const int f  = fg * 64 + tid;

    const float* Xlb = X1 + b * SEQ * H + fg * 64;                   // ascending
    const float* Glb = G1 + b * SEQ * H + fg * 64;
    const float* Xrb = X2 + b * SEQ * H + (SEQ - 1) * H + fg * 64;   // descending
    const float* Grb = G2 + b * SEQ * H + (SEQ - 1) * H + fg * 64;
    int yil = b * SEQ * LDY + f;
    int yir = b * SEQ * LDY + (SEQ - 1) * LDY + f;

    const int lr = tid >> 4;          // row sub-index (0..3)
    const int lc = (tid & 15) * 4;    // float column (16B aligned)

    auto stage = [&](int s, int buf) {
#pragma unroll
        for (int r = 0; r < 4; r++) {
            int row = r * 4 + lr;                  // timestep within stage
            int off = (s * CH + row) * H + lc;
            cp16(&sXl[buf][row][lc], Xlb + off);
            cp16(&sGl[buf][row][lc], Glb + off);
            cp16(&sXr[buf][row][lc], Xrb - off + 2 * lc - 2 * lc);  // see below
            cp16(&sGr[buf][row][lc], Grb - (s * CH + row) * H + lc);
        }
        cp_commit();
    };
    // note: rtl address = base - t*H + lc; write it plainly:
    auto stage_fix = [&](int s, int buf) {
#pragma unroll
        for (int r = 0; r < 4; r++) {
            int row = r * 4 + lr;
            int t   = s * CH + row;
            cp16(&sXl[buf][row][lc], Xlb + t * H + lc);
            cp16(&sGl[buf][row][lc], Glb + t * H + lc);
            cp16(&sXr[buf][row][lc], Xrb - t * H + lc);
            cp16(&sGr[buf][row][lc], Grb - t * H + lc);
        }
        cp_commit();
    };
    (void)stage;

    stage_fix(0, 0);
    stage_fix(1, 1);

    float hl = 0.f, hr = 0.f;
    constexpr int NB = SEQ / CH;  // 128
#pragma unroll 1
    for (int s = 0; s < NB; s++) {
        const int buf = s & 1;
        if (s == NB - 1) cp_wait0(); else cp_wait1();
        __syncthreads();   // cp.async data visible to all threads

        float xl = sXl[buf][0][tid], gl = sGl[buf][0][tid];
        float xr = sXr[buf][0][tid], gr = sGr[buf][0][tid];
#pragma unroll
        for (int j = 0; j < CH; j++) {
            float x1 = xl, g1 = gl, x2 = xr, g2 = gr;
            if (j + 1 < CH) {
                xl = sXl[buf][j + 1][tid];  gl = sGl[buf][j + 1][tid];
                xr = sXr[buf][j + 1][tid];  gr = sGr[buf][j + 1][tid];
            }
            // off-critical-path: xg = x*g ; xq = x^2(1-g)
            float a1 = x1 * g1, t1 = x1 * x1;
            float c1 = fmaf(-t1, g1, t1);
            float a2 = x2 * g2, t2 = x2 * x2;
            float c2 = fmaf(-t2, g2, t2);
            // chains: fma -> tanh (20 cyc each, interleaved)
            hl = tanh_a(fmaf(a1, hl, c1));
            Y1[yil] = hl;  yil += LDY;
            hr = tanh_a(fmaf(a2, hr, c2));
            Y2[yir] = hr;  yir -= LDY;
        }
        __syncthreads();   // all reads done before refill overwrites buf
        if (s + 2 < NB) stage_fix(s + 2, buf);
    }
    hf1[b * 256 + f] = hl;
    hf2[b * 256 + f] = hr;
}

// ---------------- launch ----------------------------------------------------
extern "C" void kernel_launch(void* const* d_in, const int* in_sizes, int n_in,
                              void* d_out, int out_size) {
    const float* x    = (const float*)d_in[0];
    const float* W_fc = (const float*)d_in[1];
    const float* b_fc = (const float*)d_in[2];
    // d_in[3]=W1, d_in[4]=b1 are mathematically dead (blending1 == identity)
    const float* W2   = (const float*)d_in[5];
    const float* b2   = (const float*)d_in[6];
    float* out = (float*)d_out;

    static float *pH1 = nullptr, *pG0 = nullptr, *pY0 = nullptr, *pG1 = nullptr, *pWr = nullptr;
    static bool inited = false;
    if (!inited) {
        cudaGetSymbolAddress((void**)&pH1, g_H1);
        cudaGetSymbolAddress((void**)&pG0, g_G0);
        cudaGetSymbolAddress((void**)&pY0, g_Y0);
        cudaGetSymbolAddress((void**)&pG1, g_G1);
        cudaGetSymbolAddress((void**)&pWr, g_Wr);
        cudaFuncSetAttribute(gemm_kernel<0>, cudaFuncAttributeMaxDynamicSharedMemorySize, GEMM_SMEM);
        cudaFuncSetAttribute(gemm_kernel<1>, cudaFuncAttributeMaxDynamicSharedMemorySize, GEMM_SMEM);
        inited = true;
    }

    float* ho = out + XXSZ;  // h_out section: 4 slots of [32,256]
    const float* Wfc_r = pWr;
    const float* W2_r  = pWr + WFC_N;

    // 0) pre-round weights to tf32 (bitwise identical to per-use cvt.rna)
    round_w_kernel<<<(WFC_N + W2_N + 255) / 256, 256>>>(W_fc, W2, pWr);
    // 1) input projection: H1 = x @ W_fc^T + b_fc           [65536,512]x[256,512]
    gemm_kernel<0><<<dim3(M0 / TBM, 2), 256, GEMM_SMEM>>>(x, Wfc_r, b_fc, pH1, M0, IN);
    // 2) layer-0 gates (shared by both directions): G0 = sigmoid(H1 @ W2_0^T + b2_0)
    gemm_kernel<1><<<dim3(M0 / TBM, 2), 256, GEMM_SMEM>>>(pH1, W2_r, b2, pG0, M0, H);
    // 3) layer-0 bidirectional scan -> Y0 (ltr half, rtl half in original t order)
    scan_bi_kernel<H><<<128, 64>>>(pH1, pG0, pY0, ho,
                                   pH1, pG0, pY0 + M0 * H, ho + BS * H);
    // 4) layer-1 gates over both halves at once: G1 = sigmoid(Y0 @ W2_1^T + b2_1)
    gemm_kernel<1><<<dim3(2 * M0 / TBM, 2), 256, GEMM_SMEM>>>(pY0, W2_r + H * H, b2 + H, pG1, 2 * M0, H);
    // 5) layer-1 scan writing straight into d_out's [b,t,2H] layout + h_out
    scan_bi_kernel<2 * H><<<128, 64>>>(pY0, pG1, out, ho + 2 * BS * H,
                                       pY0 + M0 * H, pG1 + M0 * H, out + H, ho + 3 * BS * H);
}